// round 4
// baseline (speedup 1.0000x reference)
#include <cuda_runtime.h>
#include <math.h>
#include <stdint.h>

typedef unsigned long long ull;

#define T_STEPS 128
#define BATCH   32
#define NHID    1024
#define NH2     2048
#define NTOK    10000
#define TB      (T_STEPS*BATCH)   /* 4096 */

#define KS   16     /* K-split across blocks, chunk = 64 */
#define KCH  64
#define JT   8      /* j-tiles of 128 column-pairs */
#define BJ   128    /* threads per block */

// ---------------- device scratch (no allocations allowed) ----------------
__device__ float g_emb[TB*NHID];
__device__ float g_xw0[TB*NH2];
__device__ float g_hidden[TB*NHID];
__device__ float g_states[9][BATCH*NHID];
__device__ ull   g_partC[9][KS][16][NHID];   // packed m-pair partials
__device__ ull   g_partH[9][KS][16][NHID];
__device__ int   g_cnt[9][JT];

// genotype: edge e reads states[c_ein[e]], writes states[e+1]
__constant__ int c_ein[8] = {0,1,1,1,2,5,3,5};
// act: 0 sigmoid, 1 relu, 2 tanh, 3 identity
__constant__ int c_act[8] = {0,1,1,3,2,0,2,1};

__device__ __forceinline__ float sigf(float x){ return 1.0f/(1.0f+expf(-x)); }
__device__ __forceinline__ float actf(int a, float x){
  if(a==0) return sigf(x);
  if(a==1) return fmaxf(x,0.0f);
  if(a==2) return tanhf(x);
  return x;
}
__device__ __forceinline__ void fma2(ull& d, ull a, ull b){
  asm("fma.rn.f32x2 %0, %1, %2, %0;" : "+l"(d) : "l"(a), "l"(b));
}
__device__ __forceinline__ ull dupf(float x){
  ull r; unsigned u = __float_as_uint(x);
  asm("mov.b64 %0, {%1, %1};" : "=l"(r) : "r"(u));
  return r;
}
__device__ __forceinline__ ull packf(float lo, float hi){
  ull r;
  asm("mov.b64 %0, {%1, %2};" : "=l"(r) : "r"(__float_as_uint(lo)), "r"(__float_as_uint(hi)));
  return r;
}
__device__ __forceinline__ float lo2(ull v){ return __uint_as_float((unsigned)(v & 0xffffffffull)); }
__device__ __forceinline__ float hi2(ull v){ return __uint_as_float((unsigned)(v >> 32)); }

// ---------------- embedding gather ----------------
__global__ void k_embed(const int* __restrict__ tok, const float* __restrict__ encW){
  const int tb = blockIdx.x;
  const int t  = tok[tb];
  const float4* s = reinterpret_cast<const float4*>(encW + (size_t)t*NHID);
  float4* d = reinterpret_cast<float4*>(g_emb + (size_t)tb*NHID);
  d[threadIdx.x] = s[threadIdx.x];
}

// ---------------- hoisted GEMM: g_xw0 = emb @ W0[0:1024,:] ------------------
__global__ void k_xw0(const float* __restrict__ W0){
  __shared__ float As[16][68];
  __shared__ float Bs[16][68];
  const int tid = threadIdx.x;
  const int m0 = blockIdx.y*64, n0 = blockIdx.x*64;
  const int ty = tid>>4, tx = tid&15;
  float acc[4][4] = {};
  for(int k0=0;k0<NHID;k0+=16){
    { int r = tid>>2, q = (tid&3)<<2;
      const float4 v = *reinterpret_cast<const float4*>(&g_emb[(size_t)(m0+r)*NHID + k0 + q]);
      As[q+0][r]=v.x; As[q+1][r]=v.y; As[q+2][r]=v.z; As[q+3][r]=v.w; }
    { int r = tid>>4, q = (tid&15)<<2;
      const float4 v = *reinterpret_cast<const float4*>(&W0[(size_t)(k0+r)*NH2 + n0 + q]);
      *reinterpret_cast<float4*>(&Bs[r][q]) = v; }
    __syncthreads();
    #pragma unroll
    for(int kk=0;kk<16;kk++){
      const float4 a = *reinterpret_cast<const float4*>(&As[kk][ty<<2]);
      const float4 b = *reinterpret_cast<const float4*>(&Bs[kk][tx<<2]);
      acc[0][0]+=a.x*b.x; acc[0][1]+=a.x*b.y; acc[0][2]+=a.x*b.z; acc[0][3]+=a.x*b.w;
      acc[1][0]+=a.y*b.x; acc[1][1]+=a.y*b.y; acc[1][2]+=a.y*b.z; acc[1][3]+=a.y*b.w;
      acc[2][0]+=a.z*b.x; acc[2][1]+=a.z*b.y; acc[2][2]+=a.z*b.z; acc[2][3]+=a.z*b.w;
      acc[3][0]+=a.w*b.x; acc[3][1]+=a.w*b.y; acc[3][2]+=a.w*b.z; acc[3][3]+=a.w*b.w;
    }
    __syncthreads();
  }
  #pragma unroll
  for(int i=0;i<4;i++)
    #pragma unroll
    for(int j=0;j<4;j++)
      g_xw0[(size_t)(m0+(ty<<2)+i)*NH2 + n0+(tx<<2)+j] = acc[i][j];
}

// ---------------- level GEMM: column-parallel, M-in-registers, K-split ------
// unit 0 = cell0 (A = mean(prev states) or h0 ; W = W0[1024:,:], + xw0 bias)
// unit u>=1 = edge e=u-1 (A = states[c_ein[e]] ; W = Ws[e])
__global__ __launch_bounds__(BJ) void k_lvl(const float* __restrict__ W0,
                                            const float* __restrict__ Ws,
                                            const float* __restrict__ h0in,
                                            int t, int4 uids){
  __shared__ float sh[32][68];
  __shared__ __align__(16) ull ap[KCH][16];
  __shared__ int s_elect;

  int unit;
  if      (blockIdx.y==0) unit = uids.x;
  else if (blockIdx.y==1) unit = uids.y;
  else if (blockIdx.y==2) unit = uids.z;
  else                    unit = uids.w;

  const int tid = threadIdx.x;
  const int jt  = blockIdx.x & (JT-1);
  const int ks  = blockIdx.x >> 3;
  const int k0  = ks*KCH;
  const int col = jt*BJ + tid;          // column-pair index in [0,1024)
  const int e   = unit - 1;
  const bool is0 = (unit==0);

  // -------- stage A chunk [32 rows][KCH cols] --------
  if(is0){
    if(t==0){
      for(int i=tid;i<512;i+=BJ){
        const int r=i>>4, c=(i&15)<<2;
        *reinterpret_cast<float4*>(&sh[r][c]) =
          *reinterpret_cast<const float4*>(&h0in[(size_t)r*NHID + k0 + c]);
      }
    } else {
      for(int i=tid;i<512;i+=BJ){
        const int r=i>>4, c=(i&15)<<2;
        float4 a = *reinterpret_cast<const float4*>(&g_states[1][(size_t)r*NHID + k0 + c]);
        #pragma unroll
        for(int s=2;s<9;s++){
          const float4 v = *reinterpret_cast<const float4*>(&g_states[s][(size_t)r*NHID + k0 + c]);
          a.x+=v.x; a.y+=v.y; a.z+=v.z; a.w+=v.w;
        }
        a.x*=0.125f; a.y*=0.125f; a.z*=0.125f; a.w*=0.125f;
        *reinterpret_cast<float4*>(&sh[r][c]) = a;
      }
    }
  } else {
    const float* __restrict__ sp = g_states[c_ein[e]];
    for(int i=tid;i<512;i+=BJ){
      const int r=i>>4, c=(i&15)<<2;
      *reinterpret_cast<float4*>(&sh[r][c]) =
        *reinterpret_cast<const float4*>(&sp[(size_t)r*NHID + k0 + c]);
    }
  }
  __syncthreads();

  // -------- repack to m-pairs: ap[k][mp] = (row 2mp, row 2mp+1) --------
  for(int i=tid;i<KCH*16;i+=BJ){
    const int k = i>>4, mp = i&15;
    ap[k][mp] = packf(sh[2*mp][k], sh[2*mp+1][k]);
  }
  __syncthreads();

  // -------- main loop: 1 column-pair/thread, 32 rows in registers --------
  const float* __restrict__ wc =
    (is0 ? (W0 + (size_t)(NHID + k0)*NH2) : (Ws + ((size_t)e*NHID + k0)*NH2)) + col;
  const float* __restrict__ wh = wc + NHID;

  ull accC[16], accH[16];
  #pragma unroll
  for(int i=0;i<16;i++){ accC[i]=0ull; accH[i]=0ull; }

  float pc[4], ph[4];
  #pragma unroll
  for(int i=0;i<4;i++){ pc[i]=wc[(size_t)i*NH2]; ph[i]=wh[(size_t)i*NH2]; }

  #pragma unroll 4
  for(int k=0;k<KCH;k++){
    const int r = k&3;
    float nc=0.f, nh=0.f;
    if(k+4<KCH){ nc = wc[(size_t)(k+4)*NH2]; nh = wh[(size_t)(k+4)*NH2]; }
    const ull dc = dupf(pc[r]);
    const ull dh = dupf(ph[r]);
    const ulonglong2* apk = reinterpret_cast<const ulonglong2*>(ap[k]);
    #pragma unroll
    for(int i=0;i<8;i++){
      const ulonglong2 a = apk[i];
      fma2(accC[2*i],   a.x, dc); fma2(accC[2*i+1], a.y, dc);
      fma2(accH[2*i],   a.x, dh); fma2(accH[2*i+1], a.y, dh);
    }
    pc[r]=nc; ph[r]=nh;
  }

  // -------- write partials (coalesced) --------
  {
    ull* pC = &g_partC[unit][ks][0][col];
    ull* pH = &g_partH[unit][ks][0][col];
    #pragma unroll
    for(int mp=0;mp<16;mp++){
      pC[(size_t)mp*NHID] = accC[mp];
      pH[(size_t)mp*NHID] = accH[mp];
    }
  }

  // -------- elect last block of this (unit, jt) --------
  __threadfence();
  __syncthreads();
  if(tid==0){
    const int old = atomicAdd(&g_cnt[unit][jt], 1);
    s_elect = (old == KS-1);
    if(s_elect) g_cnt[unit][jt] = 0;
    __threadfence();
  }
  __syncthreads();
  if(!s_elect) return;

  // -------- tail: reduce KS partials + nonlinearity --------
  const int act = is0 ? -1 : c_act[e];
  const int ein = is0 ? 0 : c_ein[e];
  float* __restrict__ outp = g_states[unit];

  #pragma unroll 2
  for(int mp=0;mp<16;mp++){
    float cl=0.f,ch=0.f,hl=0.f,hh=0.f;
    #pragma unroll
    for(int s=0;s<KS;s++){
      const ull v = g_partC[unit][s][mp][col];
      const ull w = g_partH[unit][s][mp][col];
      cl += lo2(v); ch += hi2(v);
      hl += lo2(w); hh += hi2(w);
    }
    const int m0 = 2*mp, m1 = 2*mp+1;
    if(is0){
      const size_t xb = ((size_t)t*BATCH)*NH2;
      cl += g_xw0[xb + (size_t)m0*NH2 + col];
      ch += g_xw0[xb + (size_t)m1*NH2 + col];
      hl += g_xw0[xb + (size_t)m0*NH2 + NHID + col];
      hh += g_xw0[xb + (size_t)m1*NH2 + NHID + col];
      float hp0, hp1;
      if(t==0){
        hp0 = h0in[(size_t)m0*NHID + col];
        hp1 = h0in[(size_t)m1*NHID + col];
      } else {
        float a0 = g_states[1][(size_t)m0*NHID + col];
        float a1 = g_states[1][(size_t)m1*NHID + col];
        #pragma unroll
        for(int s=2;s<9;s++){
          a0 += g_states[s][(size_t)m0*NHID + col];
          a1 += g_states[s][(size_t)m1*NHID + col];
        }
        hp0 = a0*0.125f; hp1 = a1*0.125f;
        g_hidden[(size_t)(t-1)*BATCH*NHID + (size_t)m0*NHID + col] = hp0;
        g_hidden[(size_t)(t-1)*BATCH*NHID + (size_t)m1*NHID + col] = hp1;
      }
      outp[(size_t)m0*NHID + col] = hp0 + sigf(cl)*(tanhf(hl)-hp0);
      outp[(size_t)m1*NHID + col] = hp1 + sigf(ch)*(tanhf(hh)-hp1);
    } else {
      const float sp0 = g_states[ein][(size_t)m0*NHID + col];
      const float sp1 = g_states[ein][(size_t)m1*NHID + col];
      outp[(size_t)m0*NHID + col] = sp0 + sigf(cl)*(actf(act,hl)-sp0);
      outp[(size_t)m1*NHID + col] = sp1 + sigf(ch)*(actf(act,hh)-sp1);
    }
  }
}

// ---------------- mean of states 1..8 -> hidden[t] (last step only) --------
__global__ void k_mean(int t){
  const int i = blockIdx.x*256 + threadIdx.x;
  float s = g_states[1][i];
  #pragma unroll
  for(int e=2;e<9;e++) s += g_states[e][i];
  g_hidden[(size_t)t*BATCH*NHID + i] = s*0.125f;
}

// ---------------- decoder: logits = hidden @ encW^T + dec_b ----------------
__global__ void k_dec(const float* __restrict__ encW, const float* __restrict__ decb,
                      float* __restrict__ out){
  __shared__ float As[16][136];
  __shared__ float Bs[16][68];
  const int tid = threadIdx.x;
  const int m0 = blockIdx.y*128, n0 = blockIdx.x*64;
  const int mg = tid>>4;
  const int ng = tid&15;
  const int m0t = mg<<3, n0t = ng<<2;

  ull acc[4][4];
  #pragma unroll
  for(int p=0;p<4;p++)
    #pragma unroll
    for(int n=0;n<4;n++) acc[p][n] = 0ull;

  for(int k0=0;k0<NHID;k0+=16){
    #pragma unroll
    for(int it=0;it<2;it++){
      const int li = tid + (it<<8);
      const int r = li>>2, q = (li&3)<<2;
      const float4 v = *reinterpret_cast<const float4*>(&g_hidden[(size_t)(m0+r)*NHID + k0 + q]);
      As[q+0][r]=v.x; As[q+1][r]=v.y; As[q+2][r]=v.z; As[q+3][r]=v.w;
    }
    {
      const int r = tid>>2, q = (tid&3)<<2;
      const int n = n0 + r;
      float4 v = make_float4(0.f,0.f,0.f,0.f);
      if(n < NTOK) v = *reinterpret_cast<const float4*>(&encW[(size_t)n*NHID + k0 + q]);
      Bs[q+0][r]=v.x; Bs[q+1][r]=v.y; Bs[q+2][r]=v.z; Bs[q+3][r]=v.w;
    }
    __syncthreads();
    #pragma unroll
    for(int kk=0;kk<16;kk++){
      const ulonglong2 a01 = *reinterpret_cast<const ulonglong2*>(&As[kk][m0t]);
      const ulonglong2 a23 = *reinterpret_cast<const ulonglong2*>(&As[kk][m0t+4]);
      const float4 b = *reinterpret_cast<const float4*>(&Bs[kk][n0t]);
      const ull b0 = dupf(b.x), b1 = dupf(b.y), b2 = dupf(b.z), b3 = dupf(b.w);
      fma2(acc[0][0], a01.x, b0); fma2(acc[0][1], a01.x, b1);
      fma2(acc[0][2], a01.x, b2); fma2(acc[0][3], a01.x, b3);
      fma2(acc[1][0], a01.y, b0); fma2(acc[1][1], a01.y, b1);
      fma2(acc[1][2], a01.y, b2); fma2(acc[1][3], a01.y, b3);
      fma2(acc[2][0], a23.x, b0); fma2(acc[2][1], a23.x, b1);
      fma2(acc[2][2], a23.x, b2); fma2(acc[2][3], a23.x, b3);
      fma2(acc[3][0], a23.y, b0); fma2(acc[3][1], a23.y, b1);
      fma2(acc[3][2], a23.y, b2); fma2(acc[3][3], a23.y, b3);
    }
    __syncthreads();
  }
  #pragma unroll
  for(int p=0;p<4;p++){
    const int m = m0 + m0t + (p<<1);
    #pragma unroll
    for(int nn=0;nn<4;nn++){
      const int n_ = n0 + n0t + nn;
      if(n_ < NTOK){
        const float bias = decb[n_];
        out[(size_t)m*NTOK + n_]       = lo2(acc[p][nn]) + bias;
        out[(size_t)(m+1)*NTOK + n_]   = hi2(acc[p][nn]) + bias;
      }
    }
  }
}

// ---------------- in-place log_softmax over each row of 10000 --------------
__global__ void k_lsm(float* __restrict__ out){
  const int row = blockIdx.x;
  float* p = out + (size_t)row*NTOK;
  __shared__ float red[256];
  float mx = -1e30f;
  for(int i=threadIdx.x;i<NTOK;i+=256) mx = fmaxf(mx, p[i]);
  red[threadIdx.x] = mx; __syncthreads();
  for(int s=128;s>0;s>>=1){
    if(threadIdx.x<s) red[threadIdx.x] = fmaxf(red[threadIdx.x], red[threadIdx.x+s]);
    __syncthreads();
  }
  mx = red[0]; __syncthreads();
  float sum = 0.f;
  for(int i=threadIdx.x;i<NTOK;i+=256) sum += expf(p[i]-mx);
  red[threadIdx.x] = sum; __syncthreads();
  for(int s=128;s>0;s>>=1){
    if(threadIdx.x<s) red[threadIdx.x] += red[threadIdx.x+s];
    __syncthreads();
  }
  const float lse = mx + logf(red[0]);
  for(int i=threadIdx.x;i<NTOK;i+=256) p[i] = p[i] - lse;
}

// ---------------- h_last copy ----------------------------------------------
__global__ void k_hlast(float* __restrict__ out){
  float4* d = reinterpret_cast<float4*>(out + (size_t)TB*NTOK);
  const float4* s = reinterpret_cast<const float4*>(g_hidden + (size_t)(T_STEPS-1)*BATCH*NHID);
  const int i = blockIdx.x*256 + threadIdx.x;
  d[i] = s[i];
}

// ---------------- launch ----------------------------------------------------
extern "C" void kernel_launch(void* const* d_in, const int* in_sizes, int n_in,
                              void* d_out, int out_size){
  const int*   tokens = (const int*)  d_in[0];
  const float* h0     = (const float*)d_in[1];
  const float* encW   = (const float*)d_in[2];
  const float* W0     = (const float*)d_in[3];
  const float* Ws     = (const float*)d_in[4];
  const float* decb   = (const float*)d_in[5];
  float* out = (float*)d_out;

  k_embed<<<TB, 256>>>(tokens, encW);
  k_xw0<<<dim3(NH2/64, TB/64), 256>>>(W0);

  for(int t=0;t<T_STEPS;t++){
    k_lvl<<<dim3(JT*KS,1), BJ>>>(W0, Ws, h0, t, make_int4(0,0,0,0));  // cell0
    k_lvl<<<dim3(JT*KS,1), BJ>>>(W0, Ws, h0, t, make_int4(1,0,0,0));  // e0
    k_lvl<<<dim3(JT*KS,3), BJ>>>(W0, Ws, h0, t, make_int4(2,3,4,0));  // e1,e2,e3
    k_lvl<<<dim3(JT*KS,2), BJ>>>(W0, Ws, h0, t, make_int4(5,7,0,0));  // e4,e6
    k_lvl<<<dim3(JT*KS,2), BJ>>>(W0, Ws, h0, t, make_int4(6,8,0,0));  // e5,e7
  }
  k_mean<<<(BATCH*NHID)/256, 256>>>(T_STEPS-1);

  k_dec<<<dim3((NTOK+63)/64, TB/128), 256>>>(encW, decb, out);
  k_lsm<<<TB, 256>>>(out);
  k_hlast<<<(BATCH*NHID/4)/256, 256>>>(out);
}

// round 5
// speedup vs baseline: 1.2871x; 1.2871x over previous
#include <cuda_runtime.h>
#include <math.h>
#include <stdint.h>

typedef unsigned long long ull;

#define T_STEPS 128
#define BATCH   32
#define NHID    1024
#define NH2     2048
#define NTOK    10000
#define TB      (T_STEPS*BATCH)
#define NB      128          /* persistent blocks */
#define KSL     4            /* K slices per edge (k-chunk 256) */

__device__ float g_emb[TB*NHID];
__device__ float g_xw0[TB*NH2];
__device__ float g_hidden[TB*NHID];
__device__ float g_states[9][BATCH*NHID];
__device__ ull   g_pC[9][KSL][16][NHID];
__device__ ull   g_pH[9][KSL][16][NHID];
__device__ int   g_cnt2;
__device__ int   g_gen;

__constant__ int c_ein[8] = {0,1,1,1,2,5,3,5};
__constant__ int c_act[8] = {0,1,1,3,2,0,2,1};
__constant__ int c_lu[5][3] = {{0,-1,-1},{1,-1,-1},{2,3,4},{5,7,-1},{6,8,-1}};
__constant__ int c_le[5] = {1,1,3,2,2};

__device__ __forceinline__ float sigf(float x){ return 1.0f/(1.0f+expf(-x)); }
__device__ __forceinline__ float actf(int a, float x){
  if(a==0) return sigf(x);
  if(a==1) return fmaxf(x,0.0f);
  if(a==2) return tanhf(x);
  return x;
}
__device__ __forceinline__ void fma2(ull& d, ull a, ull b){
  asm("fma.rn.f32x2 %0, %1, %2, %0;" : "+l"(d) : "l"(a), "l"(b));
}
__device__ __forceinline__ void add2(ull& d, ull a){
  asm("add.rn.f32x2 %0, %0, %1;" : "+l"(d) : "l"(a));
}
__device__ __forceinline__ ull dupf(float x){
  ull r; asm("mov.b64 %0, {%1, %1};" : "=l"(r) : "r"(__float_as_uint(x))); return r;
}
__device__ __forceinline__ ull packf(float lo, float hi){
  ull r; asm("mov.b64 %0, {%1, %2};" : "=l"(r) : "r"(__float_as_uint(lo)), "r"(__float_as_uint(hi))); return r;
}
__device__ __forceinline__ float lo2(ull v){ return __uint_as_float((unsigned)(v & 0xffffffffull)); }
__device__ __forceinline__ float hi2(ull v){ return __uint_as_float((unsigned)(v >> 32)); }

// grid barrier: generation counter, replay-safe (bar starts from entry value)
__device__ __forceinline__ void gbar(int& bar){
  __syncthreads();
  if(threadIdx.x==0){
    bar++;
    __threadfence();
    const int old = atomicAdd(&g_cnt2,1);
    if(old==NB-1){
      atomicExch(&g_cnt2,0);
      __threadfence();
      atomicExch(&g_gen,bar);
    } else {
      while(*(volatile int*)&g_gen - bar < 0) __nanosleep(64);
    }
  }
  __syncthreads();
  __threadfence();
}

// reduce one unit at (mp,col): sum 4 K-partials + bias/pred, activate, write state
__device__ __forceinline__ void red_unit(int unit,int mp,int col,const float* hprev,int t,
                                         float& o0, float& o1){
  float cl=0.f,ch=0.f,hl=0.f,hh=0.f;
  #pragma unroll
  for(int s=0;s<KSL;s++){
    const ull v=g_pC[unit][s][mp][col], w=g_pH[unit][s][mp][col];
    cl+=lo2(v); ch+=hi2(v); hl+=lo2(w); hh+=hi2(w);
  }
  const int m0=2*mp, m1=m0+1;
  if(unit==0){
    const size_t xb=((size_t)t*BATCH)*NH2;
    cl+=g_xw0[xb+(size_t)m0*NH2+col];      ch+=g_xw0[xb+(size_t)m1*NH2+col];
    hl+=g_xw0[xb+(size_t)m0*NH2+NHID+col]; hh+=g_xw0[xb+(size_t)m1*NH2+NHID+col];
    const float hp0=hprev[(size_t)m0*NHID+col], hp1=hprev[(size_t)m1*NHID+col];
    o0=hp0+sigf(cl)*(tanhf(hl)-hp0);
    o1=hp1+sigf(ch)*(tanhf(hh)-hp1);
  } else {
    const int e=unit-1, a=c_act[e];
    const float* sp=g_states[c_ein[e]];
    const float sp0=sp[(size_t)m0*NHID+col], sp1=sp[(size_t)m1*NHID+col];
    o0=sp0+sigf(cl)*(actf(a,hl)-sp0);
    o1=sp1+sigf(ch)*(actf(a,hh)-sp1);
  }
  g_states[unit][(size_t)m0*NHID+col]=o0;
  g_states[unit][(size_t)m1*NHID+col]=o1;
}

// ---------------- persistent recurrence kernel ------------------------------
__global__ __launch_bounds__(256,1) void k_rnn(const float* __restrict__ W0,
                                               const float* __restrict__ Ws,
                                               const float* __restrict__ h0in){
  __shared__ __align__(16) ull ap[256][16];   // 32KB: A-slice / reduce buffer
  const int tid=threadIdx.x, bid=blockIdx.x;
  const int cp = tid&31, kg = tid>>5;         // col-pair lane, k-subgroup(8x32k)
  const int jt = bid&31, ks = bid>>5;         // 32 j-tiles x 4 k-slices
  const int col = jt*32 + cp;
  const int k0  = ks*256;
  const int kb  = kg*32;
  int bar = *(volatile int*)&g_gen;

  for(int t=0;t<T_STEPS;t++){
    const float* hprev = (t==0)? h0in : (g_hidden + (size_t)(t-1)*BATCH*NHID);
    for(int L=0;L<5;L++){
      const int E=c_le[L];
      // ================= GEMM phase =================
      for(int ii=0;ii<E;ii++){
        const int unit=c_lu[L][ii];
        const float* __restrict__ A = (unit==0)? hprev : g_states[c_ein[unit-1]];
        for(int i=tid;i<4096;i+=256){
          const int k=i>>4, mp=i&15;
          ap[k][mp]=packf(A[(size_t)(2*mp)*NHID+k0+k], A[(size_t)(2*mp+1)*NHID+k0+k]);
        }
        __syncthreads();
        const float* __restrict__ wc =
          ((unit==0)? (W0+(size_t)NHID*NH2) : (Ws+(size_t)(unit-1)*NHID*NH2))
          + (size_t)(k0+kb)*NH2 + col;
        const float* __restrict__ wh = wc + NHID;
        ull aC[16], aH[16];
        #pragma unroll
        for(int i=0;i<16;i++){aC[i]=0ull;aH[i]=0ull;}
        float pc[4],ph[4];
        #pragma unroll
        for(int i=0;i<4;i++){pc[i]=wc[(size_t)i*NH2]; ph[i]=wh[(size_t)i*NH2];}
        #pragma unroll 4
        for(int k=0;k<32;k++){
          const int r=k&3;
          float nc=0.f,nh=0.f;
          if(k+4<32){ nc=wc[(size_t)(k+4)*NH2]; nh=wh[(size_t)(k+4)*NH2]; }
          const ull dc=dupf(pc[r]), dh=dupf(ph[r]);
          const ulonglong2* apk=(const ulonglong2*)ap[kb+k];
          #pragma unroll
          for(int i=0;i<8;i++){
            const ulonglong2 a=apk[i];
            fma2(aC[2*i],a.x,dc); fma2(aC[2*i+1],a.y,dc);
            fma2(aH[2*i],a.x,dh); fma2(aH[2*i+1],a.y,dh);
          }
          pc[r]=nc; ph[r]=nh;
        }
        __syncthreads();
        // in-block tree reduce across 8 k-subgroups -> kg0
        ull* red=&ap[0][0];
        #pragma unroll
        for(int half=4; half>=1; half>>=1){
          if(kg>=half && kg<2*half){
            ull* dst = red + ((size_t)((kg-half)*32+cp))*32;
            #pragma unroll
            for(int i=0;i<16;i++){ dst[i]=aC[i]; dst[16+i]=aH[i]; }
          }
          __syncthreads();
          if(kg<half){
            const ull* src = red + ((size_t)(kg*32+cp))*32;
            #pragma unroll
            for(int i=0;i<16;i++){ add2(aC[i],src[i]); add2(aH[i],src[16+i]); }
          }
          __syncthreads();
        }
        if(kg==0){
          #pragma unroll
          for(int mp=0;mp<16;mp++){
            g_pC[unit][ks][mp][col]=aC[mp];
            g_pH[unit][ks][mp][col]=aH[mp];
          }
        }
        __syncthreads();
      }
      gbar(bar);
      // ================= reduce/activate phase =================
      if(tid<128){
        const int pos=bid*128+tid;          // 16384 m-pair positions
        const int mp=pos>>10, pcol=pos&1023;
        float a0,a1,b0,b1,c0,c1;
        red_unit(c_lu[L][0],mp,pcol,hprev,t,a0,a1);
        if(E>1) red_unit(c_lu[L][1],mp,pcol,hprev,t,b0,b1);
        if(E>2) red_unit(c_lu[L][2],mp,pcol,hprev,t,c0,c1);
        if(L==4){   // hidden[t] = mean(s1..s8); a=s6, b=s8 just computed
          const int m0=2*mp, m1=m0+1;
          float h0v=a0+b0, h1v=a1+b1;
          #pragma unroll
          for(int s=1;s<6;s++){
            h0v+=g_states[s][(size_t)m0*NHID+pcol];
            h1v+=g_states[s][(size_t)m1*NHID+pcol];
          }
          h0v+=g_states[7][(size_t)m0*NHID+pcol];
          h1v+=g_states[7][(size_t)m1*NHID+pcol];
          g_hidden[(size_t)t*BATCH*NHID+(size_t)m0*NHID+pcol]=0.125f*h0v;
          g_hidden[(size_t)t*BATCH*NHID+(size_t)m1*NHID+pcol]=0.125f*h1v;
        }
      }
      gbar(bar);
    }
  }
}

// ---------------- embedding gather ----------------
__global__ void k_embed(const int* __restrict__ tok, const float* __restrict__ encW){
  const int tb=blockIdx.x, t=tok[tb];
  const float4* s=reinterpret_cast<const float4*>(encW+(size_t)t*NHID);
  float4* d=reinterpret_cast<float4*>(g_emb+(size_t)tb*NHID);
  d[threadIdx.x]=s[threadIdx.x];
}

// ---------------- hoisted GEMM: g_xw0 = emb @ W0[0:1024,:] ------------------
__global__ void k_xw0(const float* __restrict__ W0){
  __shared__ float As[16][68];
  __shared__ float Bs[16][68];
  const int tid=threadIdx.x;
  const int m0=blockIdx.y*64, n0=blockIdx.x*64;
  const int ty=tid>>4, tx=tid&15;
  float acc[4][4]={};
  for(int kk0=0;kk0<NHID;kk0+=16){
    { int r=tid>>2, q=(tid&3)<<2;
      const float4 v=*reinterpret_cast<const float4*>(&g_emb[(size_t)(m0+r)*NHID+kk0+q]);
      As[q+0][r]=v.x; As[q+1][r]=v.y; As[q+2][r]=v.z; As[q+3][r]=v.w; }
    { int r=tid>>4, q=(tid&15)<<2;
      const float4 v=*reinterpret_cast<const float4*>(&W0[(size_t)(kk0+r)*NH2+n0+q]);
      *reinterpret_cast<float4*>(&Bs[r][q])=v; }
    __syncthreads();
    #pragma unroll
    for(int kk=0;kk<16;kk++){
      const float4 a=*reinterpret_cast<const float4*>(&As[kk][ty<<2]);
      const float4 b=*reinterpret_cast<const float4*>(&Bs[kk][tx<<2]);
      acc[0][0]+=a.x*b.x; acc[0][1]+=a.x*b.y; acc[0][2]+=a.x*b.z; acc[0][3]+=a.x*b.w;
      acc[1][0]+=a.y*b.x; acc[1][1]+=a.y*b.y; acc[1][2]+=a.y*b.z; acc[1][3]+=a.y*b.w;
      acc[2][0]+=a.z*b.x; acc[2][1]+=a.z*b.y; acc[2][2]+=a.z*b.z; acc[2][3]+=a.z*b.w;
      acc[3][0]+=a.w*b.x; acc[3][1]+=a.w*b.y; acc[3][2]+=a.w*b.z; acc[3][3]+=a.w*b.w;
    }
    __syncthreads();
  }
  #pragma unroll
  for(int i=0;i<4;i++)
    #pragma unroll
    for(int j=0;j<4;j++)
      g_xw0[(size_t)(m0+(ty<<2)+i)*NH2+n0+(tx<<2)+j]=acc[i][j];
}

// ---------------- decoder: logits = hidden @ encW^T + dec_b ----------------
__global__ void k_dec(const float* __restrict__ encW, const float* __restrict__ decb,
                      float* __restrict__ out){
  __shared__ float As[16][136];
  __shared__ float Bs[16][68];
  const int tid=threadIdx.x;
  const int m0=blockIdx.y*128, n0=blockIdx.x*64;
  const int mg=tid>>4, ng=tid&15;
  const int m0t=mg<<3, n0t=ng<<2;
  ull acc[4][4];
  #pragma unroll
  for(int p=0;p<4;p++)
    #pragma unroll
    for(int n=0;n<4;n++) acc[p][n]=0ull;
  for(int kk0=0;kk0<NHID;kk0+=16){
    #pragma unroll
    for(int it=0;it<2;it++){
      const int li=tid+(it<<8);
      const int r=li>>2, q=(li&3)<<2;
      const float4 v=*reinterpret_cast<const float4*>(&g_hidden[(size_t)(m0+r)*NHID+kk0+q]);
      As[q+0][r]=v.x; As[q+1][r]=v.y; As[q+2][r]=v.z; As[q+3][r]=v.w;
    }
    {
      const int r=tid>>2, q=(tid&3)<<2;
      const int n=n0+r;
      float4 v=make_float4(0.f,0.f,0.f,0.f);
      if(n<NTOK) v=*reinterpret_cast<const float4*>(&encW[(size_t)n*NHID+kk0+q]);
      Bs[q+0][r]=v.x; Bs[q+1][r]=v.y; Bs[q+2][r]=v.z; Bs[q+3][r]=v.w;
    }
    __syncthreads();
    #pragma unroll
    for(int kk=0;kk<16;kk++){
      const ulonglong2 a01=*reinterpret_cast<const ulonglong2*>(&As[kk][m0t]);
      const ulonglong2 a23=*reinterpret_cast<const ulonglong2*>(&As[kk][m0t+4]);
      const float4 b=*reinterpret_cast<const float4*>(&Bs[kk][n0t]);
      const ull b0=dupf(b.x), b1=dupf(b.y), b2=dupf(b.z), b3=dupf(b.w);
      fma2(acc[0][0],a01.x,b0); fma2(acc[0][1],a01.x,b1);
      fma2(acc[0][2],a01.x,b2); fma2(acc[0][3],a01.x,b3);
      fma2(acc[1][0],a01.y,b0); fma2(acc[1][1],a01.y,b1);
      fma2(acc[1][2],a01.y,b2); fma2(acc[1][3],a01.y,b3);
      fma2(acc[2][0],a23.x,b0); fma2(acc[2][1],a23.x,b1);
      fma2(acc[2][2],a23.x,b2); fma2(acc[2][3],a23.x,b3);
      fma2(acc[3][0],a23.y,b0); fma2(acc[3][1],a23.y,b1);
      fma2(acc[3][2],a23.y,b2); fma2(acc[3][3],a23.y,b3);
    }
    __syncthreads();
  }
  #pragma unroll
  for(int p=0;p<4;p++){
    const int m=m0+m0t+(p<<1);
    #pragma unroll
    for(int nn=0;nn<4;nn++){
      const int n_=n0+n0t+nn;
      if(n_<NTOK){
        const float bias=decb[n_];
        out[(size_t)m*NTOK+n_]    =lo2(acc[p][nn])+bias;
        out[(size_t)(m+1)*NTOK+n_]=hi2(acc[p][nn])+bias;
      }
    }
  }
}

// ---------------- in-place log_softmax --------------------------------------
__global__ void k_lsm(float* __restrict__ out){
  const int row=blockIdx.x;
  float* p=out+(size_t)row*NTOK;
  __shared__ float red[256];
  float mx=-1e30f;
  for(int i=threadIdx.x;i<NTOK;i+=256) mx=fmaxf(mx,p[i]);
  red[threadIdx.x]=mx; __syncthreads();
  for(int s=128;s>0;s>>=1){
    if(threadIdx.x<s) red[threadIdx.x]=fmaxf(red[threadIdx.x],red[threadIdx.x+s]);
    __syncthreads();
  }
  mx=red[0]; __syncthreads();
  float sum=0.f;
  for(int i=threadIdx.x;i<NTOK;i+=256) sum+=expf(p[i]-mx);
  red[threadIdx.x]=sum; __syncthreads();
  for(int s=128;s>0;s>>=1){
    if(threadIdx.x<s) red[threadIdx.x]+=red[threadIdx.x+s];
    __syncthreads();
  }
  const float lse=mx+logf(red[0]);
  for(int i=threadIdx.x;i<NTOK;i+=256) p[i]=p[i]-lse;
}

__global__ void k_hlast(float* __restrict__ out){
  float4* d=reinterpret_cast<float4*>(out+(size_t)TB*NTOK);
  const float4* s=reinterpret_cast<const float4*>(g_hidden+(size_t)(T_STEPS-1)*BATCH*NHID);
  const int i=blockIdx.x*256+threadIdx.x;
  d[i]=s[i];
}

extern "C" void kernel_launch(void* const* d_in, const int* in_sizes, int n_in,
                              void* d_out, int out_size){
  const int*   tokens=(const int*)  d_in[0];
  const float* h0    =(const float*)d_in[1];
  const float* encW  =(const float*)d_in[2];
  const float* W0    =(const float*)d_in[3];
  const float* Ws    =(const float*)d_in[4];
  const float* decb  =(const float*)d_in[5];
  float* out=(float*)d_out;

  k_embed<<<TB,256>>>(tokens,encW);
  k_xw0<<<dim3(NH2/64,TB/64),256>>>(W0);
  k_rnn<<<NB,256>>>(W0,Ws,h0);
  k_dec<<<dim3((NTOK+63)/64,TB/128),256>>>(encW,decb,out);
  k_lsm<<<TB,256>>>(out);
  k_hlast<<<(BATCH*NHID/4)/256,256>>>(out);
}

// round 6
// speedup vs baseline: 1.7629x; 1.3697x over previous
#include <cuda_runtime.h>
#include <math.h>
#include <stdint.h>

typedef unsigned long long ull;

#define T_STEPS 128
#define BATCH   32
#define NHID    1024
#define NH2     2048
#define NTOK    10000
#define TB      (T_STEPS*BATCH)
#define NB      128          /* persistent blocks */
#define KSL     4            /* K slices (k-chunk 256) */

__device__ float g_emb[TB*NHID];
__device__ float g_xw0[TB*NH2];
__device__ float g_hidden[TB*NHID];
__device__ ull   g_sp[9][16*NHID];     // packed states: [mp][k]
__device__ ull   g_hp[16*NHID];        // packed h_prev
__device__ ull   g_pC[9][KSL][16][NHID];
__device__ ull   g_pH[9][KSL][16][NHID];
__device__ int   g_cnt2;
__device__ int   g_gen;

__constant__ int c_ein[8] = {0,1,1,1,2,5,3,5};
__constant__ int c_act[8] = {0,1,1,3,2,0,2,1};
__constant__ int c_lu[5][3] = {{0,-1,-1},{1,-1,-1},{2,3,4},{5,7,-1},{6,8,-1}};
__constant__ int c_le[5] = {1,1,3,2,2};

__device__ __forceinline__ float sigf(float x){ return 1.0f/(1.0f+expf(-x)); }
__device__ __forceinline__ float actf(int a, float x){
  if(a==0) return sigf(x);
  if(a==1) return fmaxf(x,0.0f);
  if(a==2) return tanhf(x);
  return x;
}
__device__ __forceinline__ void fma2(ull& d, ull a, ull b){
  asm("fma.rn.f32x2 %0, %1, %2, %0;" : "+l"(d) : "l"(a), "l"(b));
}
__device__ __forceinline__ void add2(ull& d, ull a){
  asm("add.rn.f32x2 %0, %0, %1;" : "+l"(d) : "l"(a));
}
__device__ __forceinline__ ull dupf(float x){
  ull r; asm("mov.b64 %0, {%1, %1};" : "=l"(r) : "r"(__float_as_uint(x))); return r;
}
__device__ __forceinline__ ull packf(float lo, float hi){
  ull r; asm("mov.b64 %0, {%1, %2};" : "=l"(r) : "r"(__float_as_uint(lo)), "r"(__float_as_uint(hi))); return r;
}
__device__ __forceinline__ float lo2(ull v){ return __uint_as_float((unsigned)(v & 0xffffffffull)); }
__device__ __forceinline__ float hi2(ull v){ return __uint_as_float((unsigned)(v >> 32)); }

// grid barrier: generation counter, replay-safe
__device__ __forceinline__ void gbar(int& bar){
  __threadfence();
  __syncthreads();
  if(threadIdx.x==0){
    bar++;
    const int old = atomicAdd(&g_cnt2,1);
    if(old==NB-1){
      atomicExch(&g_cnt2,0);
      __threadfence();
      atomicExch(&g_gen,bar);
    } else {
      while(*(volatile int*)&g_gen - bar < 0) __nanosleep(32);
    }
    __threadfence();
  }
  __syncthreads();
}

// reduce one unit at (mp,col): sum K-partials + bias/residual, activate, store packed
__device__ __forceinline__ void red_unit(int unit,int mp,int col,int t,float& o0,float& o1){
  float cl=0.f,ch=0.f,hl=0.f,hh=0.f;
  #pragma unroll
  for(int s=0;s<KSL;s++){
    const ull v=g_pC[unit][s][mp][col], w=g_pH[unit][s][mp][col];
    cl+=lo2(v); ch+=hi2(v); hl+=lo2(w); hh+=hi2(w);
  }
  const int m0=2*mp, m1=m0+1;
  if(unit==0){
    const size_t xb=((size_t)t*BATCH)*NH2;
    cl+=g_xw0[xb+(size_t)m0*NH2+col];      ch+=g_xw0[xb+(size_t)m1*NH2+col];
    hl+=g_xw0[xb+(size_t)m0*NH2+NHID+col]; hh+=g_xw0[xb+(size_t)m1*NH2+NHID+col];
    const ull hp=g_hp[mp*NHID+col];
    const float hp0=lo2(hp), hp1=hi2(hp);
    o0=hp0+sigf(cl)*(tanhf(hl)-hp0);
    o1=hp1+sigf(ch)*(tanhf(hh)-hp1);
  } else {
    const int e=unit-1, a=c_act[e];
    const ull spv=g_sp[c_ein[e]][mp*NHID+col];
    const float sp0=lo2(spv), sp1=hi2(spv);
    o0=sp0+sigf(cl)*(actf(a,hl)-sp0);
    o1=sp1+sigf(ch)*(actf(a,hh)-sp1);
  }
  g_sp[unit][mp*NHID+col]=packf(o0,o1);
}

// ---------------- pack h0 into g_hp (one-time) ------------------------------
__global__ void k_pack0(const float* __restrict__ h0in){
  const int i=blockIdx.x*256+threadIdx.x;   // 16384 positions
  const int mp=i>>10, col=i&1023;
  g_hp[mp*NHID+col]=packf(h0in[(size_t)(2*mp)*NHID+col], h0in[(size_t)(2*mp+1)*NHID+col]);
}

// ---------------- persistent recurrence kernel ------------------------------
__global__ __launch_bounds__(256,1) void k_rnn(const float* __restrict__ W0,
                                               const float* __restrict__ Ws){
  __shared__ __align__(16) ull ap[256][18];   // 36.9KB, 16B-aligned rows
  const int tid=threadIdx.x, bid=blockIdx.x;
  const int cp = tid&31, kg = tid>>5;
  const int jt = bid&31, ks = bid>>5;
  const int col = jt*32 + cp;
  const int k0  = ks*256;
  const int kb  = kg*32;
  int bar = *(volatile int*)&g_gen;

  for(int t=0;t<T_STEPS;t++){
    for(int L=0;L<5;L++){
      const int E=c_le[L];
      for(int ii=0;ii<E;ii++){
        const int unit=c_lu[L][ii];
        const ull* __restrict__ Ain = (unit==0)? g_hp : g_sp[c_ein[unit-1]];
        // coalesced packed staging: consecutive tid -> consecutive k
        for(int i=tid;i<4096;i+=256){
          const int mp=i>>8, k=i&255;
          ap[k][mp]=Ain[mp*NHID + k0 + k];
        }
        __syncthreads();
        const float* __restrict__ wc =
          ((unit==0)? (W0+(size_t)NHID*NH2) : (Ws+(size_t)(unit-1)*NHID*NH2))
          + (size_t)(k0+kb)*NH2 + col;
        const float* __restrict__ wh = wc + NHID;
        ull aC[16], aH[16];
        #pragma unroll
        for(int i=0;i<16;i++){aC[i]=0ull;aH[i]=0ull;}
        float pc[4],ph[4];
        #pragma unroll
        for(int i=0;i<4;i++){pc[i]=wc[(size_t)i*NH2]; ph[i]=wh[(size_t)i*NH2];}
        #pragma unroll 4
        for(int k=0;k<32;k++){
          const int r=k&3;
          float nc=0.f,nh=0.f;
          if(k+4<32){ nc=wc[(size_t)(k+4)*NH2]; nh=wh[(size_t)(k+4)*NH2]; }
          const ull dc=dupf(pc[r]), dh=dupf(ph[r]);
          const ulonglong2* apk=(const ulonglong2*)ap[kb+k];
          #pragma unroll
          for(int i=0;i<8;i++){
            const ulonglong2 a=apk[i];
            fma2(aC[2*i],a.x,dc); fma2(aC[2*i+1],a.y,dc);
            fma2(aH[2*i],a.x,dh); fma2(aH[2*i+1],a.y,dh);
          }
          pc[r]=nc; ph[r]=nh;
        }
        __syncthreads();
        // tree reduce across 8 k-subgroups -> kg0
        ull* red=&ap[0][0];
        #pragma unroll
        for(int half=4; half>=1; half>>=1){
          if(kg>=half && kg<2*half){
            ull* dst = red + (size_t)((kg-half)*32+cp)*33;
            #pragma unroll
            for(int i=0;i<16;i++){ dst[i]=aC[i]; dst[16+i]=aH[i]; }
          }
          __syncthreads();
          if(kg<half){
            const ull* src = red + (size_t)(kg*32+cp)*33;
            #pragma unroll
            for(int i=0;i<16;i++){ add2(aC[i],src[i]); add2(aH[i],src[16+i]); }
          }
          __syncthreads();
        }
        if(kg==0){
          #pragma unroll
          for(int mp=0;mp<16;mp++){
            g_pC[unit][ks][mp][col]=aC[mp];
            g_pH[unit][ks][mp][col]=aH[mp];
          }
        }
        __syncthreads();
      }
      gbar(bar);
      // ---- reduce/activate phase ----
      if(tid<128){
        const int pos=bid*128+tid;           // 16384 positions
        const int mp=pos>>10, pcol=pos&1023;
        float a0,a1,b0,b1,cv0,cv1;
        red_unit(c_lu[L][0],mp,pcol,t,a0,a1);
        if(E>1) red_unit(c_lu[L][1],mp,pcol,t,b0,b1);
        if(E>2) red_unit(c_lu[L][2],mp,pcol,t,cv0,cv1);
        if(L==4){   // hidden[t] = mean(s1..s8): units 6,8 = (a,b), rest from g_sp
          float h0v=a0+b0, h1v=a1+b1;
          #pragma unroll
          for(int s=1;s<6;s++){
            const ull v=g_sp[s][mp*NHID+pcol];
            h0v+=lo2(v); h1v+=hi2(v);
          }
          { const ull v=g_sp[7][mp*NHID+pcol]; h0v+=lo2(v); h1v+=hi2(v); }
          h0v*=0.125f; h1v*=0.125f;
          const int m0=2*mp;
          g_hidden[(size_t)t*BATCH*NHID+(size_t)m0*NHID+pcol]=h0v;
          g_hidden[(size_t)t*BATCH*NHID+(size_t)(m0+1)*NHID+pcol]=h1v;
          g_hp[mp*NHID+pcol]=packf(h0v,h1v);
        }
      }
      gbar(bar);
    }
  }
}

// ---------------- embedding gather ----------------
__global__ void k_embed(const int* __restrict__ tok, const float* __restrict__ encW){
  const int tb=blockIdx.x, t=tok[tb];
  const float4* s=reinterpret_cast<const float4*>(encW+(size_t)t*NHID);
  float4* d=reinterpret_cast<float4*>(g_emb+(size_t)tb*NHID);
  d[threadIdx.x]=s[threadIdx.x];
}

// ---------------- hoisted GEMM: g_xw0 = emb @ W0[0:1024,:] ------------------
__global__ void k_xw0(const float* __restrict__ W0){
  __shared__ float As[16][68];
  __shared__ float Bs[16][68];
  const int tid=threadIdx.x;
  const int m0=blockIdx.y*64, n0=blockIdx.x*64;
  const int ty=tid>>4, tx=tid&15;
  float acc[4][4]={};
  for(int kk0=0;kk0<NHID;kk0+=16){
    { int r=tid>>2, q=(tid&3)<<2;
      const float4 v=*reinterpret_cast<const float4*>(&g_emb[(size_t)(m0+r)*NHID+kk0+q]);
      As[q+0][r]=v.x; As[q+1][r]=v.y; As[q+2][r]=v.z; As[q+3][r]=v.w; }
    { int r=tid>>4, q=(tid&15)<<2;
      const float4 v=*reinterpret_cast<const float4*>(&W0[(size_t)(kk0+r)*NH2+n0+q]);
      *reinterpret_cast<float4*>(&Bs[r][q])=v; }
    __syncthreads();
    #pragma unroll
    for(int kk=0;kk<16;kk++){
      const float4 a=*reinterpret_cast<const float4*>(&As[kk][ty<<2]);
      const float4 b=*reinterpret_cast<const float4*>(&Bs[kk][tx<<2]);
      acc[0][0]+=a.x*b.x; acc[0][1]+=a.x*b.y; acc[0][2]+=a.x*b.z; acc[0][3]+=a.x*b.w;
      acc[1][0]+=a.y*b.x; acc[1][1]+=a.y*b.y; acc[1][2]+=a.y*b.z; acc[1][3]+=a.y*b.w;
      acc[2][0]+=a.z*b.x; acc[2][1]+=a.z*b.y; acc[2][2]+=a.z*b.z; acc[2][3]+=a.z*b.w;
      acc[3][0]+=a.w*b.x; acc[3][1]+=a.w*b.y; acc[3][2]+=a.w*b.z; acc[3][3]+=a.w*b.w;
    }
    __syncthreads();
  }
  #pragma unroll
  for(int i=0;i<4;i++)
    #pragma unroll
    for(int j=0;j<4;j++)
      g_xw0[(size_t)(m0+(ty<<2)+i)*NH2+n0+(tx<<2)+j]=acc[i][j];
}

// ---------------- decoder: logits = hidden @ encW^T + dec_b ----------------
__global__ void k_dec(const float* __restrict__ encW, const float* __restrict__ decb,
                      float* __restrict__ out){
  __shared__ float As[16][136];
  __shared__ float Bs[16][68];
  const int tid=threadIdx.x;
  const int m0=blockIdx.y*128, n0=blockIdx.x*64;
  const int mg=tid>>4, ng=tid&15;
  const int m0t=mg<<3, n0t=ng<<2;
  ull acc[4][4];
  #pragma unroll
  for(int p=0;p<4;p++)
    #pragma unroll
    for(int n=0;n<4;n++) acc[p][n]=0ull;
  for(int kk0=0;kk0<NHID;kk0+=16){
    #pragma unroll
    for(int it=0;it<2;it++){
      const int li=tid+(it<<8);
      const int r=li>>2, q=(li&3)<<2;
      const float4 v=*reinterpret_cast<const float4*>(&g_hidden[(size_t)(m0+r)*NHID+kk0+q]);
      As[q+0][r]=v.x; As[q+1][r]=v.y; As[q+2][r]=v.z; As[q+3][r]=v.w;
    }
    {
      const int r=tid>>2, q=(tid&3)<<2;
      const int n=n0+r;
      float4 v=make_float4(0.f,0.f,0.f,0.f);
      if(n<NTOK) v=*reinterpret_cast<const float4*>(&encW[(size_t)n*NHID+kk0+q]);
      Bs[q+0][r]=v.x; Bs[q+1][r]=v.y; Bs[q+2][r]=v.z; Bs[q+3][r]=v.w;
    }
    __syncthreads();
    #pragma unroll
    for(int kk=0;kk<16;kk++){
      const ulonglong2 a01=*reinterpret_cast<const ulonglong2*>(&As[kk][m0t]);
      const ulonglong2 a23=*reinterpret_cast<const ulonglong2*>(&As[kk][m0t+4]);
      const float4 b=*reinterpret_cast<const float4*>(&Bs[kk][n0t]);
      const ull b0=dupf(b.x), b1=dupf(b.y), b2=dupf(b.z), b3=dupf(b.w);
      fma2(acc[0][0],a01.x,b0); fma2(acc[0][1],a01.x,b1);
      fma2(acc[0][2],a01.x,b2); fma2(acc[0][3],a01.x,b3);
      fma2(acc[1][0],a01.y,b0); fma2(acc[1][1],a01.y,b1);
      fma2(acc[1][2],a01.y,b2); fma2(acc[1][3],a01.y,b3);
      fma2(acc[2][0],a23.x,b0); fma2(acc[2][1],a23.x,b1);
      fma2(acc[2][2],a23.x,b2); fma2(acc[2][3],a23.x,b3);
      fma2(acc[3][0],a23.y,b0); fma2(acc[3][1],a23.y,b1);
      fma2(acc[3][2],a23.y,b2); fma2(acc[3][3],a23.y,b3);
    }
    __syncthreads();
  }
  #pragma unroll
  for(int p=0;p<4;p++){
    const int m=m0+m0t+(p<<1);
    #pragma unroll
    for(int nn=0;nn<4;nn++){
      const int n_=n0+n0t+nn;
      if(n_<NTOK){
        const float bias=decb[n_];
        out[(size_t)m*NTOK+n_]    =lo2(acc[p][nn])+bias;
        out[(size_t)(m+1)*NTOK+n_]=hi2(acc[p][nn])+bias;
      }
    }
  }
}

// ---------------- in-place log_softmax --------------------------------------
__global__ void k_lsm(float* __restrict__ out){
  const int row=blockIdx.x;
  float* p=out+(size_t)row*NTOK;
  __shared__ float red[256];
  float mx=-1e30f;
  for(int i=threadIdx.x;i<NTOK;i+=256) mx=fmaxf(mx,p[i]);
  red[threadIdx.x]=mx; __syncthreads();
  for(int s=128;s>0;s>>=1){
    if(threadIdx.x<s) red[threadIdx.x]=fmaxf(red[threadIdx.x],red[threadIdx.x+s]);
    __syncthreads();
  }
  mx=red[0]; __syncthreads();
  float sum=0.f;
  for(int i=threadIdx.x;i<NTOK;i+=256) sum+=expf(p[i]-mx);
  red[threadIdx.x]=sum; __syncthreads();
  for(int s=128;s>0;s>>=1){
    if(threadIdx.x<s) red[threadIdx.x]+=red[threadIdx.x+s];
    __syncthreads();
  }
  const float lse=mx+logf(red[0]);
  for(int i=threadIdx.x;i<NTOK;i+=256) p[i]=p[i]-lse;
}

__global__ void k_hlast(float* __restrict__ out){
  float4* d=reinterpret_cast<float4*>(out+(size_t)TB*NTOK);
  const float4* s=reinterpret_cast<const float4*>(g_hidden+(size_t)(T_STEPS-1)*BATCH*NHID);
  const int i=blockIdx.x*256+threadIdx.x;
  d[i]=s[i];
}

extern "C" void kernel_launch(void* const* d_in, const int* in_sizes, int n_in,
                              void* d_out, int out_size){
  const int*   tokens=(const int*)  d_in[0];
  const float* h0    =(const float*)d_in[1];
  const float* encW  =(const float*)d_in[2];
  const float* W0    =(const float*)d_in[3];
  const float* Ws    =(const float*)d_in[4];
  const float* decb  =(const float*)d_in[5];
  float* out=(float*)d_out;

  k_embed<<<TB,256>>>(tokens,encW);
  k_pack0<<<64,256>>>(h0);
  k_xw0<<<dim3(NH2/64,TB/64),256>>>(W0);
  k_rnn<<<NB,256>>>(W0,Ws);
  k_dec<<<dim3((NTOK+63)/64,TB/128),256>>>(encW,decb,out);
  k_lsm<<<TB,256>>>(out);
  k_hlast<<<(BATCH*NHID/4)/256,256>>>(out);
}

// round 7
// speedup vs baseline: 1.9014x; 1.0786x over previous
#include <cuda_runtime.h>
#include <math.h>
#include <stdint.h>

typedef unsigned long long ull;

#define T_STEPS 128
#define BATCH   32
#define NHID    1024
#define NH2     2048
#define NTOK    10000
#define TB      (T_STEPS*BATCH)
#define NB      128          /* persistent blocks */
#define KSL     4            /* K slices (k-chunk 256) */
#define NT      512          /* threads per persistent block */

__device__ float g_emb[TB*NHID];
__device__ float g_xw0[TB*NH2];
__device__ float g_hidden[TB*NHID];
__device__ ull   g_sp[9][16*NHID];     // packed states: [mp][k]
__device__ ull   g_hp[16*NHID];        // packed h_prev
__device__ ull   g_pC[9][KSL][16][NHID];
__device__ ull   g_pH[9][KSL][16][NHID];
__device__ int   g_cnt2;
__device__ int   g_gen;

__constant__ int c_ein[8] = {0,1,1,1,2,5,3,5};
__constant__ int c_act[8] = {0,1,1,3,2,0,2,1};
__constant__ int c_lu[5][3] = {{0,-1,-1},{1,-1,-1},{2,3,4},{5,7,-1},{6,8,-1}};
__constant__ int c_le[5] = {1,1,3,2,2};

__device__ __forceinline__ float sigf(float x){ return 1.0f/(1.0f+expf(-x)); }
__device__ __forceinline__ float actf(int a, float x){
  if(a==0) return sigf(x);
  if(a==1) return fmaxf(x,0.0f);
  if(a==2) return tanhf(x);
  return x;
}
__device__ __forceinline__ void fma2(ull& d, ull a, ull b){
  asm("fma.rn.f32x2 %0, %1, %2, %0;" : "+l"(d) : "l"(a), "l"(b));
}
__device__ __forceinline__ void add2(ull& d, ull a){
  asm("add.rn.f32x2 %0, %0, %1;" : "+l"(d) : "l"(a));
}
__device__ __forceinline__ ull dupf(float x){
  ull r; asm("mov.b64 %0, {%1, %1};" : "=l"(r) : "r"(__float_as_uint(x))); return r;
}
__device__ __forceinline__ ull packf(float lo, float hi){
  ull r; asm("mov.b64 %0, {%1, %2};" : "=l"(r) : "r"(__float_as_uint(lo)), "r"(__float_as_uint(hi))); return r;
}
__device__ __forceinline__ float lo2(ull v){ return __uint_as_float((unsigned)(v & 0xffffffffull)); }
__device__ __forceinline__ float hi2(ull v){ return __uint_as_float((unsigned)(v >> 32)); }

// grid barrier: generation counter, replay-safe
__device__ __forceinline__ void gbar(int& bar){
  __threadfence();
  __syncthreads();
  if(threadIdx.x==0){
    bar++;
    const int old = atomicAdd(&g_cnt2,1);
    if(old==NB-1){
      atomicExch(&g_cnt2,0);
      __threadfence();
      atomicExch(&g_gen,bar);
    } else {
      while(*(volatile int*)&g_gen - bar < 0) __nanosleep(16);
    }
    __threadfence();
  }
  __syncthreads();
}

// reduce one unit at (mp,col): sum K-partials + bias/residual, activate, store packed
__device__ __forceinline__ void red_unit(int unit,int mp,int col,int t,float& o0,float& o1){
  float cl=0.f,ch=0.f,hl=0.f,hh=0.f;
  #pragma unroll
  for(int s=0;s<KSL;s++){
    const ull v=g_pC[unit][s][mp][col], w=g_pH[unit][s][mp][col];
    cl+=lo2(v); ch+=hi2(v); hl+=lo2(w); hh+=hi2(w);
  }
  const int m0=2*mp, m1=m0+1;
  if(unit==0){
    const size_t xb=((size_t)t*BATCH)*NH2;
    cl+=g_xw0[xb+(size_t)m0*NH2+col];      ch+=g_xw0[xb+(size_t)m1*NH2+col];
    hl+=g_xw0[xb+(size_t)m0*NH2+NHID+col]; hh+=g_xw0[xb+(size_t)m1*NH2+NHID+col];
    const ull hp=g_hp[mp*NHID+col];
    const float hp0=lo2(hp), hp1=hi2(hp);
    o0=hp0+sigf(cl)*(tanhf(hl)-hp0);
    o1=hp1+sigf(ch)*(tanhf(hh)-hp1);
  } else {
    const int e=unit-1, a=c_act[e];
    const ull spv=g_sp[c_ein[e]][mp*NHID+col];
    const float sp0=lo2(spv), sp1=hi2(spv);
    o0=sp0+sigf(cl)*(actf(a,hl)-sp0);
    o1=sp1+sigf(ch)*(actf(a,hh)-sp1);
  }
  g_sp[unit][mp*NHID+col]=packf(o0,o1);
}

// ---------------- pack h0 into g_hp (one-time) ------------------------------
__global__ void k_pack0(const float* __restrict__ h0in){
  const int i=blockIdx.x*256+threadIdx.x;
  const int mp=i>>10, col=i&1023;
  g_hp[mp*NHID+col]=packf(h0in[(size_t)(2*mp)*NHID+col], h0in[(size_t)(2*mp+1)*NHID+col]);
}

// ---------------- persistent recurrence kernel ------------------------------
// block(512): cp=tid&31 col lane, kg=(tid>>5)&7 k-subgroup, mh=tid>>8 mp-half
// grid(128):  jt=bid&31 j-tile(32 col-pairs), ks=bid>>5 K-slice(256 k)
__global__ __launch_bounds__(NT,1) void k_rnn(const float* __restrict__ W0,
                                              const float* __restrict__ Ws){
  __shared__ __align__(16) ull ap[256][18];   // 36.9KB: A-stage / reduce buffer
  __shared__ ull rbuf[2][128];
  const int tid=threadIdx.x, bid=blockIdx.x;
  const int cp = tid&31, kg = (tid>>5)&7, mh = tid>>8;
  const int jt = bid&31, ks = bid>>5;
  const int col = jt*32 + cp;
  const int k0  = ks*256;
  const int kb  = kg*32;
  const int mpb = mh*8;
  int bar = *(volatile int*)&g_gen;

  for(int t=0;t<T_STEPS;t++){
    for(int L=0;L<5;L++){
      const int E=c_le[L];
      for(int ii=0;ii<E;ii++){
        const int unit=c_lu[L][ii];
        const ull* __restrict__ Ain = (unit==0)? g_hp : g_sp[c_ein[unit-1]];
        // coalesced packed staging: 4096 ull, 8 per thread
        for(int i=tid;i<4096;i+=NT){
          const int mp=i>>8, k=i&255;
          ap[k][mp]=Ain[mp*NHID + k0 + k];
        }
        __syncthreads();
        const float* __restrict__ wc =
          ((unit==0)? (W0+(size_t)NHID*NH2) : (Ws+(size_t)(unit-1)*NHID*NH2))
          + (size_t)(k0+kb)*NH2 + col;
        const float* __restrict__ wh = wc + NHID;
        ull aC[8], aH[8];
        #pragma unroll
        for(int i=0;i<8;i++){aC[i]=0ull;aH[i]=0ull;}
        float pc[4],ph[4];
        #pragma unroll
        for(int i=0;i<4;i++){pc[i]=wc[(size_t)i*NH2]; ph[i]=wh[(size_t)i*NH2];}
        #pragma unroll 4
        for(int k=0;k<32;k++){
          const int r=k&3;
          float nc=0.f,nh=0.f;
          if(k+4<32){ nc=wc[(size_t)(k+4)*NH2]; nh=wh[(size_t)(k+4)*NH2]; }
          const ull dc=dupf(pc[r]), dh=dupf(ph[r]);
          const ulonglong2* apk=(const ulonglong2*)&ap[kb+k][mpb];
          #pragma unroll
          for(int i=0;i<4;i++){
            const ulonglong2 a=apk[i];
            fma2(aC[2*i],a.x,dc); fma2(aC[2*i+1],a.y,dc);
            fma2(aH[2*i],a.x,dh); fma2(aH[2*i+1],a.y,dh);
          }
          pc[r]=nc; ph[r]=nh;
        }
        __syncthreads();
        // tree reduce across 8 kg subgroups -> kg0 (per cp,mh)
        ull* red=&ap[0][0];
        #pragma unroll
        for(int half=4; half>=1; half>>=1){
          if(kg>=half && kg<2*half){
            ull* dst = red + (size_t)(((kg-half)<<6)+(mh<<5)+cp)*17;
            #pragma unroll
            for(int i=0;i<8;i++){ dst[i]=aC[i]; dst[8+i]=aH[i]; }
          }
          __syncthreads();
          if(kg<half){
            const ull* src = red + (size_t)((kg<<6)+(mh<<5)+cp)*17;
            #pragma unroll
            for(int i=0;i<8;i++){ add2(aC[i],src[i]); add2(aH[i],src[8+i]); }
          }
          __syncthreads();
        }
        if(kg==0){
          #pragma unroll
          for(int i=0;i<8;i++){
            g_pC[unit][ks][mpb+i][col]=aC[i];
            g_pH[unit][ks][mpb+i][col]=aH[i];
          }
        }
        __syncthreads();
      }
      gbar(bar);
      // ---- reduce/activate phase: (position, unit-slot) across 512 threads ----
      {
        const int pslot = tid>>7;            // 0..3
        const int ppos  = tid&127;
        const int pos   = bid*128 + ppos;    // 16384 positions
        const int mp=pos>>10, pcol=pos&1023;
        if(pslot<E){
          float o0,o1;
          red_unit(c_lu[L][pslot],mp,pcol,t,o0,o1);
          if(L==4) rbuf[pslot][ppos]=packf(o0,o1);
        }
        if(L==4){
          __syncthreads();
          if(pslot==3){   // hidden[t] = mean(s1..s8); s6,s8 fresh in rbuf
            const ull va=rbuf[0][ppos], vb=rbuf[1][ppos];
            float h0v=lo2(va)+lo2(vb), h1v=hi2(va)+hi2(vb);
            #pragma unroll
            for(int s=1;s<6;s++){
              const ull v=g_sp[s][mp*NHID+pcol];
              h0v+=lo2(v); h1v+=hi2(v);
            }
            { const ull v=g_sp[7][mp*NHID+pcol]; h0v+=lo2(v); h1v+=hi2(v); }
            h0v*=0.125f; h1v*=0.125f;
            const int m0=2*mp;
            g_hidden[(size_t)t*BATCH*NHID+(size_t)m0*NHID+pcol]=h0v;
            g_hidden[(size_t)t*BATCH*NHID+(size_t)(m0+1)*NHID+pcol]=h1v;
            g_hp[mp*NHID+pcol]=packf(h0v,h1v);
          }
        }
      }
      gbar(bar);
    }
  }
}

// ---------------- embedding gather ----------------
__global__ void k_embed(const int* __restrict__ tok, const float* __restrict__ encW){
  const int tb=blockIdx.x, t=tok[tb];
  const float4* s=reinterpret_cast<const float4*>(encW+(size_t)t*NHID);
  float4* d=reinterpret_cast<float4*>(g_emb+(size_t)tb*NHID);
  d[threadIdx.x]=s[threadIdx.x];
}

// ---------------- xw0: emb(4096x1024) @ W0[0:1024,:] (fp32x2, 128x64 tile) --
__global__ void k_xw0f(const float* __restrict__ W0){
  __shared__ float As[16][136];
  __shared__ float Bs[16][68];
  const int tid=threadIdx.x;
  const int m0=blockIdx.y*128, n0=blockIdx.x*64;
  const int mg=tid>>4, ng=tid&15;
  const int m0t=mg<<3, n0t=ng<<2;
  ull acc[4][4];
  #pragma unroll
  for(int p=0;p<4;p++)
    #pragma unroll
    for(int n=0;n<4;n++) acc[p][n]=0ull;
  for(int kk0=0;kk0<NHID;kk0+=16){
    #pragma unroll
    for(int it=0;it<2;it++){
      const int li=tid+(it<<8);
      const int r=li>>2, q=(li&3)<<2;
      const float4 v=*reinterpret_cast<const float4*>(&g_emb[(size_t)(m0+r)*NHID+kk0+q]);
      As[q+0][r]=v.x; As[q+1][r]=v.y; As[q+2][r]=v.z; As[q+3][r]=v.w;
    }
    {
      const int r=tid>>4, q=(tid&15)<<2;   // B: [k][n] rows of W0, coalesced
      const float4 v=*reinterpret_cast<const float4*>(&W0[(size_t)(kk0+r)*NH2+n0+q]);
      *reinterpret_cast<float4*>(&Bs[r][q])=v;
    }
    __syncthreads();
    #pragma unroll
    for(int kk=0;kk<16;kk++){
      const ulonglong2 a01=*reinterpret_cast<const ulonglong2*>(&As[kk][m0t]);
      const ulonglong2 a23=*reinterpret_cast<const ulonglong2*>(&As[kk][m0t+4]);
      const float4 b=*reinterpret_cast<const float4*>(&Bs[kk][n0t]);
      const ull b0=dupf(b.x), b1=dupf(b.y), b2=dupf(b.z), b3=dupf(b.w);
      fma2(acc[0][0],a01.x,b0); fma2(acc[0][1],a01.x,b1);
      fma2(acc[0][2],a01.x,b2); fma2(acc[0][3],a01.x,b3);
      fma2(acc[1][0],a01.y,b0); fma2(acc[1][1],a01.y,b1);
      fma2(acc[1][2],a01.y,b2); fma2(acc[1][3],a01.y,b3);
      fma2(acc[2][0],a23.x,b0); fma2(acc[2][1],a23.x,b1);
      fma2(acc[2][2],a23.x,b2); fma2(acc[2][3],a23.x,b3);
      fma2(acc[3][0],a23.y,b0); fma2(acc[3][1],a23.y,b1);
      fma2(acc[3][2],a23.y,b2); fma2(acc[3][3],a23.y,b3);
    }
    __syncthreads();
  }
  #pragma unroll
  for(int p=0;p<4;p++){
    const int m=m0+m0t+(p<<1);
    #pragma unroll
    for(int nn=0;nn<4;nn++){
      const int n_=n0+n0t+nn;
      g_xw0[(size_t)m*NH2+n_]    =lo2(acc[p][nn]);
      g_xw0[(size_t)(m+1)*NH2+n_]=hi2(acc[p][nn]);
    }
  }
}

// ---------------- decoder: logits = hidden @ encW^T + dec_b ----------------
__global__ void k_dec(const float* __restrict__ encW, const float* __restrict__ decb,
                      float* __restrict__ out){
  __shared__ float As[16][136];
  __shared__ float Bs[16][68];
  const int tid=threadIdx.x;
  const int m0=blockIdx.y*128, n0=blockIdx.x*64;
  const int mg=tid>>4, ng=tid&15;
  const int m0t=mg<<3, n0t=ng<<2;
  ull acc[4][4];
  #pragma unroll
  for(int p=0;p<4;p++)
    #pragma unroll
    for(int n=0;n<4;n++) acc[p][n]=0ull;
  for(int kk0=0;kk0<NHID;kk0+=16){
    #pragma unroll
    for(int it=0;it<2;it++){
      const int li=tid+(it<<8);
      const int r=li>>2, q=(li&3)<<2;
      const float4 v=*reinterpret_cast<const float4*>(&g_hidden[(size_t)(m0+r)*NHID+kk0+q]);
      As[q+0][r]=v.x; As[q+1][r]=v.y; As[q+2][r]=v.z; As[q+3][r]=v.w;
    }
    {
      const int r=tid>>2, q=(tid&3)<<2;
      const int n=n0+r;
      float4 v=make_float4(0.f,0.f,0.f,0.f);
      if(n<NTOK) v=*reinterpret_cast<const float4*>(&encW[(size_t)n*NHID+kk0+q]);
      Bs[q+0][r]=v.x; Bs[q+1][r]=v.y; Bs[q+2][r]=v.z; Bs[q+3][r]=v.w;
    }
    __syncthreads();
    #pragma unroll
    for(int kk=0;kk<16;kk++){
      const ulonglong2 a01=*reinterpret_cast<const ulonglong2*>(&As[kk][m0t]);
      const ulonglong2 a23=*reinterpret_cast<const ulonglong2*>(&As[kk][m0t+4]);
      const float4 b=*reinterpret_cast<const float4*>(&Bs[kk][n0t]);
      const ull b0=dupf(b.x), b1=dupf(b.y), b2=dupf(b.z), b3=dupf(b.w);
      fma2(acc[0][0],a01.x,b0); fma2(acc[0][1],a01.x,b1);
      fma2(acc[0][2],a01.x,b2); fma2(acc[0][3],a01.x,b3);
      fma2(acc[1][0],a01.y,b0); fma2(acc[1][1],a01.y,b1);
      fma2(acc[1][2],a01.y,b2); fma2(acc[1][3],a01.y,b3);
      fma2(acc[2][0],a23.x,b0); fma2(acc[2][1],a23.x,b1);
      fma2(acc[2][2],a23.x,b2); fma2(acc[2][3],a23.x,b3);
      fma2(acc[3][0],a23.y,b0); fma2(acc[3][1],a23.y,b1);
      fma2(acc[3][2],a23.y,b2); fma2(acc[3][3],a23.y,b3);
    }
    __syncthreads();
  }
  #pragma unroll
  for(int p=0;p<4;p++){
    const int m=m0+m0t+(p<<1);
    #pragma unroll
    for(int nn=0;nn<4;nn++){
      const int n_=n0+n0t+nn;
      if(n_<NTOK){
        const float bias=decb[n_];
        out[(size_t)m*NTOK+n_]    =lo2(acc[p][nn])+bias;
        out[(size_t)(m+1)*NTOK+n_]=hi2(acc[p][nn])+bias;
      }
    }
  }
}

// ---------------- in-place log_softmax --------------------------------------
__global__ void k_lsm(float* __restrict__ out){
  const int row=blockIdx.x;
  float* p=out+(size_t)row*NTOK;
  __shared__ float red[256];
  float mx=-1e30f;
  for(int i=threadIdx.x;i<NTOK;i+=256) mx=fmaxf(mx,p[i]);
  red[threadIdx.x]=mx; __syncthreads();
  for(int s=128;s>0;s>>=1){
    if(threadIdx.x<s) red[threadIdx.x]=fmaxf(red[threadIdx.x],red[threadIdx.x+s]);
    __syncthreads();
  }
  mx=red[0]; __syncthreads();
  float sum=0.f;
  for(int i=threadIdx.x;i<NTOK;i+=256) sum+=expf(p[i]-mx);
  red[threadIdx.x]=sum; __syncthreads();
  for(int s=128;s>0;s>>=1){
    if(threadIdx.x<s) red[threadIdx.x]+=red[threadIdx.x+s];
    __syncthreads();
  }
  const float lse=mx+logf(red[0]);
  for(int i=threadIdx.x;i<NTOK;i+=256) p[i]=p[i]-lse;
}

__global__ void k_hlast(float* __restrict__ out){
  float4* d=reinterpret_cast<float4*>(out+(size_t)TB*NTOK);
  const float4* s=reinterpret_cast<const float4*>(g_hidden+(size_t)(T_STEPS-1)*BATCH*NHID);
  const int i=blockIdx.x*256+threadIdx.x;
  d[i]=s[i];
}

extern "C" void kernel_launch(void* const* d_in, const int* in_sizes, int n_in,
                              void* d_out, int out_size){
  const int*   tokens=(const int*)  d_in[0];
  const float* h0    =(const float*)d_in[1];
  const float* encW  =(const float*)d_in[2];
  const float* W0    =(const float*)d_in[3];
  const float* Ws    =(const float*)d_in[4];
  const float* decb  =(const float*)d_in[5];
  float* out=(float*)d_out;

  k_embed<<<TB,256>>>(tokens,encW);
  k_pack0<<<64,256>>>(h0);
  k_xw0f<<<dim3(NH2/64,TB/128),256>>>(W0);
  k_rnn<<<NB,NT>>>(W0,Ws);
  k_dec<<<dim3((NTOK+63)/64,TB/128),256>>>(encW,decb,out);
  k_lsm<<<TB,256>>>(out);
  k_hlast<<<(BATCH*NHID/4)/256,256>>>(out);
}